// round 15
// baseline (speedup 1.0000x reference)
#include <cuda_runtime.h>
#include <stdint.h>
#include <math.h>

#define NN   8192
#define WPR  256          // 8192 bits / 32 per word
#define ESTR 96           // ELL stride (max degree of Poisson(32) graph ~60)

// ---------------- device scratch (static, no allocation) ----------------
// g_adj0 is zero at load; scatter sets bits, ELL build re-zeroes after reading,
// so every kernel_launch invocation (and graph replay) sees identical state.
static __device__ uint32_t g_adj0[NN * WPR];
static __device__ int      g_colsE[NN * ESTR];   // ELL columns (3 MB)
static __device__ int      g_ne[NN];             // neighbors per row
static __device__ uint8_t  g_flagsA[NN * ESTR];
static __device__ uint8_t  g_flagsB[NN * ESTR];
static __device__ float    g_dinv0[NN];
static __device__ float    g_dinvA[NN];
static __device__ float    g_dinvB[NN];
static __device__ float    g_za[NN * 64];
static __device__ float    g_zb[NN * 64];
static __device__ float    g_gt[NN * 64];

// ---------------- Threefry-2x32 (exact JAX constants/rounds) ----------------
__host__ __device__ __forceinline__ void tf2x32(uint32_t k0, uint32_t k1,
                                                uint32_t &x0, uint32_t &x1) {
  uint32_t k2 = k0 ^ k1 ^ 0x1BD11BDAu;
  x0 += k0; x1 += k1;
#define TF_RND(r) { x0 += x1; x1 = (x1 << (r)) | (x1 >> (32 - (r))); x1 ^= x0; }
  TF_RND(13) TF_RND(15) TF_RND(26) TF_RND(6)
  x0 += k1; x1 += k2 + 1u;
  TF_RND(17) TF_RND(29) TF_RND(16) TF_RND(24)
  x0 += k2; x1 += k0 + 2u;
  TF_RND(13) TF_RND(15) TF_RND(26) TF_RND(6)
  x0 += k0; x1 += k1 + 3u;
  TF_RND(17) TF_RND(29) TF_RND(16) TF_RND(24)
  x0 += k1; x1 += k2 + 4u;
  TF_RND(13) TF_RND(15) TF_RND(26) TF_RND(6)
  x0 += k2; x1 += k0 + 5u;
#undef TF_RND
}

// partitionable threefry: element n -> counter (0, n); bits = out0 ^ out1
__device__ __forceinline__ float jax_uniform01(uint32_t k0, uint32_t k1, uint32_t n) {
  uint32_t x0 = 0u, x1 = n;
  tf2x32(k0, k1, x0, x1);
  uint32_t bits = x0 ^ x1;
  return __uint_as_float((bits >> 9) | 0x3f800000u) - 1.0f;
}

// ---------------- device bodies ----------------
// raw GEMM: gt = zin @ W (no scaling). 128 threads, 16 rows per gemm-block.
template <int KIN, int C>
__device__ __forceinline__ void gemm_body(const float *__restrict__ zin,
                                          const float *__restrict__ W,
                                          float *__restrict__ gt, int bid, float *sh) {
  const int NC = C / 32;
  float *Ws = sh;
  float *Zs = sh + KIN * C;
  int t = threadIdx.x;
  int row0 = bid * 16;
  for (int i = t; i < KIN * C / 4; i += 128)
    ((float4 *)Ws)[i] = ((const float4 *)W)[i];
  for (int i = t; i < 16 * KIN / 4; i += 128)
    ((float4 *)Zs)[i] = ((const float4 *)(zin + row0 * KIN))[i];
  __syncthreads();

  int warp = t >> 5, lane = t & 31;
  float acc[4][NC];
#pragma unroll
  for (int r = 0; r < 4; r++)
#pragma unroll
    for (int c = 0; c < NC; c++) acc[r][c] = 0.f;

#pragma unroll 4
  for (int k = 0; k < KIN; k++) {
    float wv[NC];
#pragma unroll
    for (int c = 0; c < NC; c++) wv[c] = Ws[k * C + lane + c * 32];
#pragma unroll
    for (int r = 0; r < 4; r++) {
      float zv = Zs[(warp * 4 + r) * KIN + k];
#pragma unroll
      for (int c = 0; c < NC; c++) acc[r][c] += zv * wv[c];
    }
  }
#pragma unroll
  for (int r = 0; r < 4; r++) {
    int row = row0 + warp * 4 + r;
#pragma unroll
    for (int c = 0; c < NC; c++) gt[row * C + lane + c * 32] = acc[r][c];
  }
}

// warp-per-row ELL build from bitmask (ascending j -> deterministic),
// then zero the bitmask row so the next replay starts clean.
__device__ __forceinline__ void ell_body(uint32_t *__restrict__ adj,
                                         int *__restrict__ colsE, int *__restrict__ ne,
                                         float *__restrict__ dinv0, int row) {
  int lane = threadIdx.x & 31;
  uint32_t wv[8];
  int cnt = 0;
#pragma unroll
  for (int k = 0; k < 8; k++) {
    wv[k] = adj[row * WPR + lane * 8 + k];
    cnt += __popc(wv[k]);
  }
  int inc = cnt;
#pragma unroll
  for (int d = 1; d < 32; d <<= 1) {
    int n = __shfl_up_sync(0xffffffffu, inc, d);
    if (lane >= d) inc += n;
  }
  int total = __shfl_sync(0xffffffffu, inc, 31);
  int p = row * ESTR + inc - cnt;
#pragma unroll
  for (int k = 0; k < 8; k++) {
    uint32_t m = wv[k];
    while (m) {
      int bit = __ffs(m) - 1; m &= m - 1;
      colsE[p++] = ((lane * 8 + k) << 5) + bit;
    }
  }
  // self-clean for next replay (32B-aligned uint4 stores)
  uint4 z4 = make_uint4(0u, 0u, 0u, 0u);
  uint4 *dst = (uint4 *)(adj + row * WPR + lane * 8);
  dst[0] = z4; dst[1] = z4;
  if (lane == 0) { ne[row] = total; dinv0[row] = rsqrtf((float)total + 1.0f); }
}

// lane-per-edge resample: warp per row, z_i staged in shared, one edge per lane.
// Threefry/sigmoid run on all 32 lanes in parallel. Count via ballot+popc.
__device__ __forceinline__ void res_body(const int *__restrict__ colsE,
                                         const int *__restrict__ nearr,
                                         const float *__restrict__ z,
                                         uint8_t *__restrict__ flags,
                                         float *__restrict__ dinvL, int row,
                                         uint32_t kb0, uint32_t kb1,
                                         float *zi_sh) {
  int lane = threadIdx.x & 31;
  int ne = nearr[row];
  // stage z_i (64 floats) once per warp
  ((float2 *)zi_sh)[lane] = ((const float2 *)(z + row * 64))[lane];
  __syncwarp();
  const float4 *s4 = (const float4 *)zi_sh;

  int kcount = 0;
  int nIter = (ne + 31) >> 5;          // warp-uniform (1 or 2)
  for (int it = 0; it < nIter; it++) {
    int e = it * 32 + lane;
    bool active = (e < ne);
    int j = active ? colsE[row * ESTR + e] : 0;
    const float4 *zj4 = (const float4 *)(z + j * 64);
    float acc[4] = {0.f, 0.f, 0.f, 0.f};
#pragma unroll
    for (int k = 0; k < 16; k++) {
      float4 a = zj4[k];
      float4 bb = s4[k];               // broadcast LDS
      acc[k & 3] = fmaf(a.x, bb.x, fmaf(a.y, bb.y, fmaf(a.z, bb.z, fmaf(a.w, bb.w, acc[k & 3]))));
    }
    float d = (acc[0] + acc[1]) + (acc[2] + acc[3]);
    uint8_t f = 0;
    if (active) {
      float p = 1.0f / (1.0f + expf(-d));
      float u = jax_uniform01(kb0, kb1, (uint32_t)row * (uint32_t)NN + (uint32_t)j);
      f = (u < p) ? 1 : 0;
      flags[row * ESTR + e] = f;
    }
    unsigned mk = __ballot_sync(0xffffffffu, f != 0);
    kcount += __popc(mk);
  }
  if (lane == 0) dinvL[row] = rsqrtf((float)kcount + 1.0f);
}

// ---------------- kernels ----------------
// scatter with per-block dtype probe (first 512 u64 words of edge buffer)
__global__ void k_scatter(uint32_t *adj0, const void *ev, int n) {
  __shared__ int s_is64;
  if (threadIdx.x < 32) {
    const unsigned long long *q = (const unsigned long long *)ev;
    int lane = threadIdx.x;
    bool big = false;
    for (int k = lane; k < 512; k += 32) big |= (q[k] > 8191ull);
    unsigned m = __ballot_sync(0xffffffffu, big);
    if (lane == 0) s_is64 = (m == 0u);
  }
  __syncthreads();
  int k = blockIdx.x * blockDim.x + threadIdx.x;
  if (k >= n) return;
  int r, c;
  if (s_is64) {
    const long long *e = (const long long *)ev;
    r = (int)e[k]; c = (int)e[k + n];
  } else {
    const int *e = (const int *)ev;
    r = e[k]; c = e[k + n];
  }
  atomicOr(&adj0[r * WPR + (c >> 5)], 1u << (c & 31));
}

// fused: blocks [0,512) gemm0(x,W0); blocks [512,2560) ELL build (+mask clear)
__global__ void k_ellgemm0(const float *x, const float *W0, float *gt,
                           uint32_t *adj0, int *colsE, int *ne, float *dinv0) {
  __shared__ float sh[128 * 64 + 16 * 128];     // 40 KB
  if (blockIdx.x < NN / 16) {
    gemm_body<128, 64>(x, W0, gt, blockIdx.x, sh);
  } else {
    int row = (blockIdx.x - NN / 16) * 4 + (threadIdx.x >> 5);
    ell_body(adj0, colsE, ne, dinv0, row);
  }
}

// fused: blocks [0,512) gemm(z,W) for next layer; blocks [512,2560) resample(z)
template <int KIN, int C>
__global__ void k_resgemm(const float *z, const float *W, float *gt,
                          const int *colsE, const int *ne,
                          uint8_t *flags, float *dinvL, uint32_t kb0, uint32_t kb1) {
  __shared__ float sh[KIN * C + 16 * KIN];      // gemm needs all; res uses 256 floats
  if (blockIdx.x < NN / 16) {
    gemm_body<KIN, C>(z, W, gt, blockIdx.x, sh);
  } else {
    int warp = threadIdx.x >> 5;
    int row = (blockIdx.x - NN / 16) * 4 + warp;
    res_body(colsE, ne, z, flags, dinvL, row, kb0, kb1, sh + warp * 64);
  }
}

// warp-per-row aggregate with shared-staged (w, j) metadata.
// z_i = dropout(relu(dv_i*(dv_i*g_i + sum_e w_e*g_{j_e}) + b)), w_e = keep ? dv_j : 0
template <int C, bool F>
__global__ void k_agg(const int *__restrict__ colsE, const int *__restrict__ nearr,
                      const uint8_t *__restrict__ flags, const float *__restrict__ gt,
                      const float *__restrict__ dinvL, const float *__restrict__ b,
                      float *__restrict__ zout, uint32_t kd0, uint32_t kd1) {
  __shared__ int2 sw[8][ESTR];          // warp-private (w bits, j)
  int warp = threadIdx.x >> 5, lane = threadIdx.x & 31;
  int i = blockIdx.x * 8 + warp;
  int ne = nearr[i];
  int base = i * ESTR;
  float dvi = dinvL[i];

  // stage (w, j) once: lane covers edges lane, lane+32, lane+64
#pragma unroll
  for (int s = 0; s < 3; s++) {
    int e = s * 32 + lane;
    int j = 0; float w = 0.f;
    if (e < ne) {
      j = colsE[base + e];
      bool keep = !F || (flags[base + e] != 0);
      w = keep ? dinvL[j] : 0.f;
    }
    sw[warp][e] = make_int2(__float_as_int(w), j);
  }
  __syncwarp();

  const int2 *row_sw = sw[warp];
  if (C == 64) {
    const float2 *gt2 = (const float2 *)gt;
    float2 gi = gt2[i * 32 + lane];
    float ax[4] = {dvi * gi.x, 0.f, 0.f, 0.f};
    float ay[4] = {dvi * gi.y, 0.f, 0.f, 0.f};
    int e = 0;
    for (; e + 4 <= ne; e += 4) {
#pragma unroll
      for (int k = 0; k < 4; k++) {
        int2 p = row_sw[e + k];
        float w = __int_as_float(p.x);
        float2 gj = gt2[p.y * 32 + lane];
        ax[k] = fmaf(w, gj.x, ax[k]);
        ay[k] = fmaf(w, gj.y, ay[k]);
      }
    }
    for (; e < ne; e++) {
      int2 p = row_sw[e];
      float w = __int_as_float(p.x);
      float2 gj = gt2[p.y * 32 + lane];
      ax[0] = fmaf(w, gj.x, ax[0]);
      ay[0] = fmaf(w, gj.y, ay[0]);
    }
    float accx = (ax[0] + ax[1]) + (ax[2] + ax[3]);
    float accy = (ay[0] + ay[1]) + (ay[2] + ay[3]);
    int c = lane * 2;
    float v0 = fmaxf(dvi * accx + b[c], 0.f);
    float v1 = fmaxf(dvi * accy + b[c + 1], 0.f);
    float u0 = jax_uniform01(kd0, kd1, (uint32_t)(i * 64 + c));
    float u1 = jax_uniform01(kd0, kd1, (uint32_t)(i * 64 + c + 1));
    float2 out;
    out.x = (u0 < 0.9f) ? (v0 / 0.9f) : 0.f;
    out.y = (u1 < 0.9f) ? (v1 / 0.9f) : 0.f;
    ((float2 *)zout)[i * 32 + lane] = out;
  } else {
    float a[4] = {dvi * gt[i * 32 + lane], 0.f, 0.f, 0.f};
    int e = 0;
    for (; e + 4 <= ne; e += 4) {
#pragma unroll
      for (int k = 0; k < 4; k++) {
        int2 p = row_sw[e + k];
        float w = __int_as_float(p.x);
        a[k] = fmaf(w, gt[p.y * 32 + lane], a[k]);
      }
    }
    for (; e < ne; e++) {
      int2 p = row_sw[e];
      a[0] = fmaf(__int_as_float(p.x), gt[p.y * 32 + lane], a[0]);
    }
    float acc = (a[0] + a[1]) + (a[2] + a[3]);
    float v = fmaxf(dvi * acc + b[lane], 0.f);
    float u = jax_uniform01(kd0, kd1, (uint32_t)(i * 32 + lane));
    zout[i * 32 + lane] = (u < 0.9f) ? (v / 0.9f) : 0.f;
  }
}

// ---------------- launch ----------------
extern "C" void kernel_launch(void *const *d_in, const int *in_sizes, int n_in,
                              void *d_out, int out_size) {
  const float *x  = (const float *)d_in[0];
  const float *W0 = (const float *)d_in[1];
  const float *b0 = (const float *)d_in[2];
  const float *W1 = (const float *)d_in[3];
  const float *b1 = (const float *)d_in[4];
  const float *W2 = (const float *)d_in[5];
  const float *b2 = (const float *)d_in[6];
  const void  *ei = (const void  *)d_in[7];
  int nE = in_sizes[7] / 2;

  // JAX key schedule (partitionable threefry):
  // r_i = block((0,42),(0,i)); kd = block(r_i,(0,0)); kb = block(r_i,(0,1))
  uint32_t kd[3][2], kb[3][2];
  for (int i = 0; i < 3; i++) {
    uint32_t f0 = 0u, f1 = (uint32_t)i;
    tf2x32(0u, 42u, f0, f1);
    uint32_t a0 = 0u, a1 = 0u; tf2x32(f0, f1, a0, a1);
    uint32_t c0 = 0u, c1 = 1u; tf2x32(f0, f1, c0, c1);
    kd[i][0] = a0; kd[i][1] = a1;
    kb[i][0] = c0; kb[i][1] = c1;
  }

  uint32_t *adj0; int *colsE, *ne;
  uint8_t *flA, *flB; float *dv0, *dvA, *dvB, *za, *zb, *gt;
  cudaGetSymbolAddress((void **)&adj0,  g_adj0);
  cudaGetSymbolAddress((void **)&colsE, g_colsE);
  cudaGetSymbolAddress((void **)&ne,    g_ne);
  cudaGetSymbolAddress((void **)&flA,   g_flagsA);
  cudaGetSymbolAddress((void **)&flB,   g_flagsB);
  cudaGetSymbolAddress((void **)&dv0,   g_dinv0);
  cudaGetSymbolAddress((void **)&dvA,   g_dinvA);
  cudaGetSymbolAddress((void **)&dvB,   g_dinvB);
  cudaGetSymbolAddress((void **)&za,    g_za);
  cudaGetSymbolAddress((void **)&zb,    g_zb);
  cudaGetSymbolAddress((void **)&gt,    g_gt);

  const int FUSED_GRID = NN / 16 + NN / 4;   // 512 gemm blocks + 2048 row blocks

  // mask is all-zero here (load-time init / self-clean from previous run)
  k_scatter<<<(nE + 255) / 256, 256>>>(adj0, ei, nE);

  // ELL build (+mask self-clean) || gemm0
  k_ellgemm0<<<FUSED_GRID, 128>>>(x, W0, gt, adj0, colsE, ne, dv0);

  // layer 0 aggregate -> za
  k_agg<64, false><<<NN / 8, 256>>>(colsE, ne, flA, gt, dv0, b0, za, kd[0][0], kd[0][1]);

  // resample(za) || gemm1(za,W1)
  k_resgemm<64, 64><<<FUSED_GRID, 128>>>(za, W1, gt, colsE, ne, flA, dvA,
                                         kb[0][0], kb[0][1]);

  // layer 1 aggregate -> zb
  k_agg<64, true><<<NN / 8, 256>>>(colsE, ne, flA, gt, dvA, b1, zb, kd[1][0], kd[1][1]);

  // resample(zb) || gemm2(zb,W2)
  k_resgemm<64, 32><<<FUSED_GRID, 128>>>(zb, W2, gt, colsE, ne, flB, dvB,
                                         kb[1][0], kb[1][1]);

  // layer 2 aggregate -> d_out
  k_agg<32, true><<<NN / 8, 256>>>(colsE, ne, flB, gt, dvB, b2, (float *)d_out,
                                   kd[2][0], kd[2][1]);
}

// round 16
// speedup vs baseline: 1.3150x; 1.3150x over previous
#include <cuda_runtime.h>
#include <stdint.h>
#include <math.h>

#define NN   8192
#define WPR  256          // 8192 bits / 32 per word
#define ESTR 96           // ELL stride (max degree of Poisson(32) graph ~60)

// ---------------- device scratch (static, no allocation) ----------------
// g_adj0 is zero at load; scatter sets bits, ELL build re-zeroes after reading,
// so every kernel_launch invocation (and graph replay) sees identical state.
static __device__ uint32_t g_adj0[NN * WPR];
static __device__ int      g_colsE[NN * ESTR];   // ELL columns (3 MB)
static __device__ int      g_ne[NN];             // neighbors per row
static __device__ uint8_t  g_flagsA[NN * ESTR];
static __device__ uint8_t  g_flagsB[NN * ESTR];
static __device__ float    g_dinv0[NN];
static __device__ float    g_dinvA[NN];
static __device__ float    g_dinvB[NN];
static __device__ float    g_za[NN * 64];
static __device__ float    g_zb[NN * 64];
static __device__ float    g_gt[NN * 64];

// ---------------- Threefry-2x32 (exact JAX constants/rounds) ----------------
__host__ __device__ __forceinline__ void tf2x32(uint32_t k0, uint32_t k1,
                                                uint32_t &x0, uint32_t &x1) {
  uint32_t k2 = k0 ^ k1 ^ 0x1BD11BDAu;
  x0 += k0; x1 += k1;
#define TF_RND(r) { x0 += x1; x1 = (x1 << (r)) | (x1 >> (32 - (r))); x1 ^= x0; }
  TF_RND(13) TF_RND(15) TF_RND(26) TF_RND(6)
  x0 += k1; x1 += k2 + 1u;
  TF_RND(17) TF_RND(29) TF_RND(16) TF_RND(24)
  x0 += k2; x1 += k0 + 2u;
  TF_RND(13) TF_RND(15) TF_RND(26) TF_RND(6)
  x0 += k0; x1 += k1 + 3u;
  TF_RND(17) TF_RND(29) TF_RND(16) TF_RND(24)
  x0 += k1; x1 += k2 + 4u;
  TF_RND(13) TF_RND(15) TF_RND(26) TF_RND(6)
  x0 += k2; x1 += k0 + 5u;
#undef TF_RND
}

// partitionable threefry: element n -> counter (0, n); bits = out0 ^ out1
__device__ __forceinline__ float jax_uniform01(uint32_t k0, uint32_t k1, uint32_t n) {
  uint32_t x0 = 0u, x1 = n;
  tf2x32(k0, k1, x0, x1);
  uint32_t bits = x0 ^ x1;
  return __uint_as_float((bits >> 9) | 0x3f800000u) - 1.0f;
}

// ---------------- device bodies ----------------
// raw GEMM: gt = zin @ W (no scaling). 128 threads, 16 rows per gemm-block.
template <int KIN, int C>
__device__ __forceinline__ void gemm_body(const float *__restrict__ zin,
                                          const float *__restrict__ W,
                                          float *__restrict__ gt, int bid, float *sh) {
  const int NC = C / 32;
  float *Ws = sh;
  float *Zs = sh + KIN * C;
  int t = threadIdx.x;
  int row0 = bid * 16;
  for (int i = t; i < KIN * C / 4; i += 128)
    ((float4 *)Ws)[i] = ((const float4 *)W)[i];
  for (int i = t; i < 16 * KIN / 4; i += 128)
    ((float4 *)Zs)[i] = ((const float4 *)(zin + row0 * KIN))[i];
  __syncthreads();

  int warp = t >> 5, lane = t & 31;
  float acc[4][NC];
#pragma unroll
  for (int r = 0; r < 4; r++)
#pragma unroll
    for (int c = 0; c < NC; c++) acc[r][c] = 0.f;

#pragma unroll 4
  for (int k = 0; k < KIN; k++) {
    float wv[NC];
#pragma unroll
    for (int c = 0; c < NC; c++) wv[c] = Ws[k * C + lane + c * 32];
#pragma unroll
    for (int r = 0; r < 4; r++) {
      float zv = Zs[(warp * 4 + r) * KIN + k];
#pragma unroll
      for (int c = 0; c < NC; c++) acc[r][c] += zv * wv[c];
    }
  }
#pragma unroll
  for (int r = 0; r < 4; r++) {
    int row = row0 + warp * 4 + r;
#pragma unroll
    for (int c = 0; c < NC; c++) gt[row * C + lane + c * 32] = acc[r][c];
  }
}

// warp-per-row ELL build from bitmask (ascending j -> deterministic),
// then zero the bitmask row so the next replay starts clean.
__device__ __forceinline__ void ell_body(uint32_t *__restrict__ adj,
                                         int *__restrict__ colsE, int *__restrict__ ne,
                                         float *__restrict__ dinv0, int row) {
  int lane = threadIdx.x & 31;
  uint32_t wv[8];
  int cnt = 0;
#pragma unroll
  for (int k = 0; k < 8; k++) {
    wv[k] = adj[row * WPR + lane * 8 + k];
    cnt += __popc(wv[k]);
  }
  int inc = cnt;
#pragma unroll
  for (int d = 1; d < 32; d <<= 1) {
    int n = __shfl_up_sync(0xffffffffu, inc, d);
    if (lane >= d) inc += n;
  }
  int total = __shfl_sync(0xffffffffu, inc, 31);
  int p = row * ESTR + inc - cnt;
#pragma unroll
  for (int k = 0; k < 8; k++) {
    uint32_t m = wv[k];
    while (m) {
      int bit = __ffs(m) - 1; m &= m - 1;
      colsE[p++] = ((lane * 8 + k) << 5) + bit;
    }
  }
  // self-clean for next replay (32B-aligned uint4 stores)
  uint4 z4 = make_uint4(0u, 0u, 0u, 0u);
  uint4 *dst = (uint4 *)(adj + row * WPR + lane * 8);
  dst[0] = z4; dst[1] = z4;
  if (lane == 0) { ne[row] = total; dinv0[row] = rsqrtf((float)total + 1.0f); }
}

// two-phase resample: warp per row.
// Phase 1 (R14 layout): 8 lanes/edge, coalesced 128-bit loads, shfl-8 dot -> d_sh.
// Phase 2: lane-per-edge threefry+sigmoid (all 32 lanes busy). Count via ballot.
// sh layout per warp: [0,64) z_i floats, [64, 64+ESTR) d values.
__device__ __forceinline__ void res_body(const int *__restrict__ colsE,
                                         const int *__restrict__ nearr,
                                         const float *__restrict__ z,
                                         uint8_t *__restrict__ flags,
                                         float *__restrict__ dinvL, int row,
                                         uint32_t kb0, uint32_t kb1,
                                         float *sh) {
  int lane = threadIdx.x & 31;
  int ne = nearr[row];
  float *zi_sh = sh;
  float *d_sh = sh + 64;
  ((float2 *)zi_sh)[lane] = ((const float2 *)(z + row * 64))[lane];
  __syncwarp();
  const float4 *s4 = (const float4 *)zi_sh;

  int g = lane >> 3, s = lane & 7;      // 4 edge-slots x 8 lanes
  int nIter = (ne + 3) >> 2;            // warp-uniform
  for (int it = 0; it < nIter; it++) {
    int e = it * 4 + g;
    bool active = (e < ne);
    int j = active ? colsE[row * ESTR + e] : 0;
    const float4 *zj4 = (const float4 *)(z + j * 64);
    float4 a0 = zj4[s],     b0 = s4[s];
    float4 a1 = zj4[s + 8], b1 = s4[s + 8];
    float d = a0.x * b0.x + a0.y * b0.y + a0.z * b0.z + a0.w * b0.w
            + a1.x * b1.x + a1.y * b1.y + a1.z * b1.z + a1.w * b1.w;
#pragma unroll
    for (int o = 4; o; o >>= 1) d += __shfl_down_sync(0xffffffffu, d, o, 8);
    if (active && s == 0) d_sh[e] = d;
  }
  __syncwarp();

  int kcount = 0;
  int nIt2 = (ne + 31) >> 5;            // warp-uniform (1 or 2)
  for (int it = 0; it < nIt2; it++) {
    int e = it * 32 + lane;
    bool active = (e < ne);
    uint8_t f = 0;
    if (active) {
      int j = colsE[row * ESTR + e];
      float d = d_sh[e];
      float p = 1.0f / (1.0f + expf(-d));
      float u = jax_uniform01(kb0, kb1, (uint32_t)row * (uint32_t)NN + (uint32_t)j);
      f = (u < p) ? 1 : 0;
      flags[row * ESTR + e] = f;
    }
    unsigned mk = __ballot_sync(0xffffffffu, f != 0);
    kcount += __popc(mk);
  }
  if (lane == 0) dinvL[row] = rsqrtf((float)kcount + 1.0f);
}

// ---------------- kernels ----------------
// scatter with per-block dtype probe (first 512 u64 words of edge buffer)
__global__ void k_scatter(uint32_t *adj0, const void *ev, int n) {
  __shared__ int s_is64;
  if (threadIdx.x < 32) {
    const unsigned long long *q = (const unsigned long long *)ev;
    int lane = threadIdx.x;
    bool big = false;
    for (int k = lane; k < 512; k += 32) big |= (q[k] > 8191ull);
    unsigned m = __ballot_sync(0xffffffffu, big);
    if (lane == 0) s_is64 = (m == 0u);
  }
  __syncthreads();
  int k = blockIdx.x * blockDim.x + threadIdx.x;
  if (k >= n) return;
  int r, c;
  if (s_is64) {
    const long long *e = (const long long *)ev;
    r = (int)e[k]; c = (int)e[k + n];
  } else {
    const int *e = (const int *)ev;
    r = e[k]; c = e[k + n];
  }
  atomicOr(&adj0[r * WPR + (c >> 5)], 1u << (c & 31));
}

// fused: blocks [0,512) gemm0(x,W0); blocks [512,2560) ELL build (+mask clear)
__global__ void __launch_bounds__(128)
k_ellgemm0(const float *x, const float *W0, float *gt,
           uint32_t *adj0, int *colsE, int *ne, float *dinv0) {
  __shared__ float sh[128 * 64 + 16 * 128];     // 40 KB
  if (blockIdx.x < NN / 16) {
    gemm_body<128, 64>(x, W0, gt, blockIdx.x, sh);
  } else {
    int row = (blockIdx.x - NN / 16) * 4 + (threadIdx.x >> 5);
    ell_body(adj0, colsE, ne, dinv0, row);
  }
}

// fused: blocks [0,512) gemm(z,W) for next layer; blocks [512,2560) resample(z)
template <int KIN, int C>
__global__ void __launch_bounds__(128)
k_resgemm(const float *z, const float *W, float *gt,
          const int *colsE, const int *ne,
          uint8_t *flags, float *dinvL, uint32_t kb0, uint32_t kb1) {
  __shared__ float sh[KIN * C + 16 * KIN];      // gemm uses all; res uses 4*(64+ESTR)
  if (blockIdx.x < NN / 16) {
    gemm_body<KIN, C>(z, W, gt, blockIdx.x, sh);
  } else {
    int warp = threadIdx.x >> 5;
    int row = (blockIdx.x - NN / 16) * 4 + warp;
    res_body(colsE, ne, z, flags, dinvL, row, kb0, kb1, sh + warp * (64 + ESTR));
  }
}

// warp-per-row aggregate with shared-staged (w, j) metadata.
// z_i = dropout(relu(dv_i*(dv_i*g_i + sum_e w_e*g_{j_e}) + b)), w_e = keep ? dv_j : 0
template <int C, bool F>
__global__ void k_agg(const int *__restrict__ colsE, const int *__restrict__ nearr,
                      const uint8_t *__restrict__ flags, const float *__restrict__ gt,
                      const float *__restrict__ dinvL, const float *__restrict__ b,
                      float *__restrict__ zout, uint32_t kd0, uint32_t kd1) {
  __shared__ int2 sw[8][ESTR];          // warp-private (w bits, j)
  int warp = threadIdx.x >> 5, lane = threadIdx.x & 31;
  int i = blockIdx.x * 8 + warp;
  int ne = nearr[i];
  int base = i * ESTR;
  float dvi = dinvL[i];

  // stage (w, j) once: lane covers edges lane, lane+32, lane+64
#pragma unroll
  for (int s = 0; s < 3; s++) {
    int e = s * 32 + lane;
    int j = 0; float w = 0.f;
    if (e < ne) {
      j = colsE[base + e];
      bool keep = !F || (flags[base + e] != 0);
      w = keep ? dinvL[j] : 0.f;
    }
    sw[warp][e] = make_int2(__float_as_int(w), j);
  }
  __syncwarp();

  const int2 *row_sw = sw[warp];
  if (C == 64) {
    const float2 *gt2 = (const float2 *)gt;
    float2 gi = gt2[i * 32 + lane];
    float ax[4] = {dvi * gi.x, 0.f, 0.f, 0.f};
    float ay[4] = {dvi * gi.y, 0.f, 0.f, 0.f};
    int e = 0;
    for (; e + 4 <= ne; e += 4) {
#pragma unroll
      for (int k = 0; k < 4; k++) {
        int2 p = row_sw[e + k];
        float w = __int_as_float(p.x);
        float2 gj = gt2[p.y * 32 + lane];
        ax[k] = fmaf(w, gj.x, ax[k]);
        ay[k] = fmaf(w, gj.y, ay[k]);
      }
    }
    for (; e < ne; e++) {
      int2 p = row_sw[e];
      float w = __int_as_float(p.x);
      float2 gj = gt2[p.y * 32 + lane];
      ax[0] = fmaf(w, gj.x, ax[0]);
      ay[0] = fmaf(w, gj.y, ay[0]);
    }
    float accx = (ax[0] + ax[1]) + (ax[2] + ax[3]);
    float accy = (ay[0] + ay[1]) + (ay[2] + ay[3]);
    int c = lane * 2;
    float v0 = fmaxf(dvi * accx + b[c], 0.f);
    float v1 = fmaxf(dvi * accy + b[c + 1], 0.f);
    float u0 = jax_uniform01(kd0, kd1, (uint32_t)(i * 64 + c));
    float u1 = jax_uniform01(kd0, kd1, (uint32_t)(i * 64 + c + 1));
    float2 out;
    out.x = (u0 < 0.9f) ? (v0 / 0.9f) : 0.f;
    out.y = (u1 < 0.9f) ? (v1 / 0.9f) : 0.f;
    ((float2 *)zout)[i * 32 + lane] = out;
  } else {
    float a[4] = {dvi * gt[i * 32 + lane], 0.f, 0.f, 0.f};
    int e = 0;
    for (; e + 4 <= ne; e += 4) {
#pragma unroll
      for (int k = 0; k < 4; k++) {
        int2 p = row_sw[e + k];
        float w = __int_as_float(p.x);
        a[k] = fmaf(w, gt[p.y * 32 + lane], a[k]);
      }
    }
    for (; e < ne; e++) {
      int2 p = row_sw[e];
      a[0] = fmaf(__int_as_float(p.x), gt[p.y * 32 + lane], a[0]);
    }
    float acc = (a[0] + a[1]) + (a[2] + a[3]);
    float v = fmaxf(dvi * acc + b[lane], 0.f);
    float u = jax_uniform01(kd0, kd1, (uint32_t)(i * 32 + lane));
    zout[i * 32 + lane] = (u < 0.9f) ? (v / 0.9f) : 0.f;
  }
}

// ---------------- launch ----------------
extern "C" void kernel_launch(void *const *d_in, const int *in_sizes, int n_in,
                              void *d_out, int out_size) {
  const float *x  = (const float *)d_in[0];
  const float *W0 = (const float *)d_in[1];
  const float *b0 = (const float *)d_in[2];
  const float *W1 = (const float *)d_in[3];
  const float *b1 = (const float *)d_in[4];
  const float *W2 = (const float *)d_in[5];
  const float *b2 = (const float *)d_in[6];
  const void  *ei = (const void  *)d_in[7];
  int nE = in_sizes[7] / 2;

  // JAX key schedule (partitionable threefry):
  // r_i = block((0,42),(0,i)); kd = block(r_i,(0,0)); kb = block(r_i,(0,1))
  uint32_t kd[3][2], kb[3][2];
  for (int i = 0; i < 3; i++) {
    uint32_t f0 = 0u, f1 = (uint32_t)i;
    tf2x32(0u, 42u, f0, f1);
    uint32_t a0 = 0u, a1 = 0u; tf2x32(f0, f1, a0, a1);
    uint32_t c0 = 0u, c1 = 1u; tf2x32(f0, f1, c0, c1);
    kd[i][0] = a0; kd[i][1] = a1;
    kb[i][0] = c0; kb[i][1] = c1;
  }

  uint32_t *adj0; int *colsE, *ne;
  uint8_t *flA, *flB; float *dv0, *dvA, *dvB, *za, *zb, *gt;
  cudaGetSymbolAddress((void **)&adj0,  g_adj0);
  cudaGetSymbolAddress((void **)&colsE, g_colsE);
  cudaGetSymbolAddress((void **)&ne,    g_ne);
  cudaGetSymbolAddress((void **)&flA,   g_flagsA);
  cudaGetSymbolAddress((void **)&flB,   g_flagsB);
  cudaGetSymbolAddress((void **)&dv0,   g_dinv0);
  cudaGetSymbolAddress((void **)&dvA,   g_dinvA);
  cudaGetSymbolAddress((void **)&dvB,   g_dinvB);
  cudaGetSymbolAddress((void **)&za,    g_za);
  cudaGetSymbolAddress((void **)&zb,    g_zb);
  cudaGetSymbolAddress((void **)&gt,    g_gt);

  const int FUSED_GRID = NN / 16 + NN / 4;   // 512 gemm blocks + 2048 row blocks

  // mask is all-zero here (load-time init / self-clean from previous run)
  k_scatter<<<(nE + 255) / 256, 256>>>(adj0, ei, nE);

  // ELL build (+mask self-clean) || gemm0
  k_ellgemm0<<<FUSED_GRID, 128>>>(x, W0, gt, adj0, colsE, ne, dv0);

  // layer 0 aggregate -> za
  k_agg<64, false><<<NN / 8, 256>>>(colsE, ne, flA, gt, dv0, b0, za, kd[0][0], kd[0][1]);

  // resample(za) || gemm1(za,W1)
  k_resgemm<64, 64><<<FUSED_GRID, 128>>>(za, W1, gt, colsE, ne, flA, dvA,
                                         kb[0][0], kb[0][1]);

  // layer 1 aggregate -> zb
  k_agg<64, true><<<NN / 8, 256>>>(colsE, ne, flA, gt, dvA, b1, zb, kd[1][0], kd[1][1]);

  // resample(zb) || gemm2(zb,W2)
  k_resgemm<64, 32><<<FUSED_GRID, 128>>>(zb, W2, gt, colsE, ne, flB, dvB,
                                         kb[1][0], kb[1][1]);

  // layer 2 aggregate -> d_out
  k_agg<32, true><<<NN / 8, 256>>>(colsE, ne, flB, gt, dvB, b2, (float *)d_out,
                                   kd[2][0], kd[2][1]);
}